// round 10
// baseline (speedup 1.0000x reference)
#include <cuda_runtime.h>

// DyDepthwiseConvAtten fused: dynamic 3-tap depthwise conv along C + LayerNorm.
// B*N = 102400 rows, C = 256. R9 = R3 (warp-per-row, 8 ch/lane, ALL constants
// in registers, grid 1184) + SINGLE-PHASE reduction: LN mean/var are derived
// algebraically from S=sum(v), SS=sum(v^2), P1=sum(v[c-1]v[c]),
// P2=sum(v[c-1]v[c+1]) so all 7 row-sums (3 weights + 4 stats) reduce in ONE
// 5-stage shuffle tree with 7 interleaved chains, instead of two serialized
// trees. Cuts ~130+ cyc of exposed SHFL latency per row.

#define C_DIM  256
#define LN_EPS 1e-5f
#define FULL   0xFFFFFFFFu

__global__ __launch_bounds__(256)
void dydwconv_ln_kernel(const float* __restrict__ q,
                        const float* __restrict__ v,
                        const float* __restrict__ Ww,     // [3,256]
                        const float* __restrict__ bw,     // [3]
                        const float* __restrict__ gamma,  // [256]
                        const float* __restrict__ beta,   // [256]
                        float* __restrict__ out,
                        int rows, int total_warps)
{
    const int warp_g = (blockIdx.x * blockDim.x + threadIdx.x) >> 5;
    const int lane   = threadIdx.x & 31;
    const int cbase  = lane * 8;

    // ---- hoisted constants (registers) ----
    float W0[8], W1[8], W2[8], G[8], Bt[8];
    {
        const float4* p;
        float4 a, b;
        p = (const float4*)(Ww + 0 * C_DIM + cbase); a = p[0]; b = p[1];
        W0[0]=a.x; W0[1]=a.y; W0[2]=a.z; W0[3]=a.w; W0[4]=b.x; W0[5]=b.y; W0[6]=b.z; W0[7]=b.w;
        p = (const float4*)(Ww + 1 * C_DIM + cbase); a = p[0]; b = p[1];
        W1[0]=a.x; W1[1]=a.y; W1[2]=a.z; W1[3]=a.w; W1[4]=b.x; W1[5]=b.y; W1[6]=b.z; W1[7]=b.w;
        p = (const float4*)(Ww + 2 * C_DIM + cbase); a = p[0]; b = p[1];
        W2[0]=a.x; W2[1]=a.y; W2[2]=a.z; W2[3]=a.w; W2[4]=b.x; W2[5]=b.y; W2[6]=b.z; W2[7]=b.w;
        p = (const float4*)(gamma + cbase); a = p[0]; b = p[1];
        G[0]=a.x; G[1]=a.y; G[2]=a.z; G[3]=a.w; G[4]=b.x; G[5]=b.y; G[6]=b.z; G[7]=b.w;
        p = (const float4*)(beta + cbase); a = p[0]; b = p[1];
        Bt[0]=a.x; Bt[1]=a.y; Bt[2]=a.z; Bt[3]=a.w; Bt[4]=b.x; Bt[5]=b.y; Bt[6]=b.z; Bt[7]=b.w;
    }
    const float bw0 = bw[0], bw1 = bw[1], bw2 = bw[2];

    for (int row = warp_g; row < rows; row += total_warps) {
        const size_t base = (size_t)row * C_DIM + cbase;

        const float4 qa = ((const float4*)(q + base))[0];
        const float4 qb = ((const float4*)(q + base))[1];
        const float4 va = ((const float4*)(v + base))[0];
        const float4 vb = ((const float4*)(v + base))[1];
        float Q[8] = {qa.x, qa.y, qa.z, qa.w, qb.x, qb.y, qb.z, qb.w};
        float V[8] = {va.x, va.y, va.z, va.w, vb.x, vb.y, vb.z, vb.w};

        // ---- halo + edge broadcasts (independent shuffles, issued early) ----
        float vl   = __shfl_up_sync(FULL, V[7], 1);     // v[cbase-1]
        float vr   = __shfl_down_sync(FULL, V[0], 1);   // v[cbase+8]
        const float v0   = __shfl_sync(FULL, V[0], 0);  // v[0]
        const float v255 = __shfl_sync(FULL, V[7], 31); // v[255]
        if (lane == 0)  vl = 0.f;
        if (lane == 31) vr = 0.f;

        // ---- per-lane partials for all 7 row sums ----
        float p0 = 0.f, p1 = 0.f, p2 = 0.f;   // dynamic weights
        float S = 0.f, SS = 0.f;              // sum(v), sum(v^2)
        #pragma unroll
        for (int i = 0; i < 8; i++) {
            p0 = fmaf(Q[i], W0[i], p0);
            p1 = fmaf(Q[i], W1[i], p1);
            p2 = fmaf(Q[i], W2[i], p2);
            S += V[i];
            SS = fmaf(V[i], V[i], SS);
        }
        // P1 = sum v[c-1]*v[c] ; P2 = sum v[c-1]*v[c+1] over this lane's c range
        float P1 = vl * V[0];
        float P2 = vl * V[1];
        #pragma unroll
        for (int i = 1; i < 8; i++) P1 = fmaf(V[i - 1], V[i], P1);
        #pragma unroll
        for (int i = 1; i < 7; i++) P2 = fmaf(V[i - 1], V[i + 1], P2);
        P2 = fmaf(V[6], vr, P2);

        // ---- ONE shuffle tree, 7 interleaved chains ----
        #pragma unroll
        for (int off = 16; off > 0; off >>= 1) {
            p0 += __shfl_xor_sync(FULL, p0, off);
            p1 += __shfl_xor_sync(FULL, p1, off);
            p2 += __shfl_xor_sync(FULL, p2, off);
            S  += __shfl_xor_sync(FULL, S,  off);
            SS += __shfl_xor_sync(FULL, SS, off);
            P1 += __shfl_xor_sync(FULL, P1, off);
            P2 += __shfl_xor_sync(FULL, P2, off);
        }

        const float w0 = bw0 + p0;
        const float w1 = bw1 + p1;
        const float w2 = bw2 + p2;

        // ---- LN stats, closed form ----
        const float sum_o = w0 * (S - v255) + w1 * S + w2 * (S - v0);
        const float mean  = sum_o * (1.0f / C_DIM);
        float sum_o2 = (w0 * w0 + w1 * w1 + w2 * w2) * SS
                     - (w0 * w0) * (v255 * v255)
                     - (w2 * w2) * (v0 * v0)
                     + 2.0f * (w0 * w1 + w1 * w2) * P1
                     + 2.0f * (w0 * w2) * P2;
        const float var = sum_o2 * (1.0f / C_DIM) - mean * mean;
        const float inv = rsqrtf(var + LN_EPS);

        // ---- conv + normalize + affine + store (off the reduction path) ----
        float4 oa, ob;
        float* po = &oa.x;
        float carry = vl;
        #pragma unroll
        for (int i = 0; i < 8; i++) {
            const float cur = V[i];
            const float nxt = (i < 7) ? V[i + 1] : vr;
            const float o   = carry * w0 + cur * w1 + nxt * w2;
            const float r   = (o - mean) * inv * G[i] + Bt[i];
            if (i < 4) po[i] = r; else (&ob.x)[i - 4] = r;
            carry = cur;
        }
        ((float4*)(out + base))[0] = oa;
        ((float4*)(out + base))[1] = ob;
    }
}

extern "C" void kernel_launch(void* const* d_in, const int* in_sizes, int n_in,
                              void* d_out, int out_size)
{
    const float* q     = (const float*)d_in[0];
    const float* v     = (const float*)d_in[1];
    const float* Ww    = (const float*)d_in[2];
    const float* bw    = (const float*)d_in[3];
    const float* gamma = (const float*)d_in[4];
    const float* beta  = (const float*)d_in[5];
    float* out = (float*)d_out;

    const int rows = in_sizes[0] / C_DIM;        // 102400
    const int grid = 1184;                       // 148 SMs * 8 CTAs (R3 config)
    const int total_warps = grid * (256 / 32);   // 9472
    dydwconv_ln_kernel<<<grid, 256>>>(q, v, Ww, bw, gamma, beta, out,
                                      rows, total_warps);
}

// round 11
// speedup vs baseline: 1.0734x; 1.0734x over previous
#include <cuda_runtime.h>

// DyDepthwiseConvAtten fused: dynamic 3-tap depthwise conv along C + LayerNorm.
// B*N = 102400 rows, C = 256. R10 = R3 body EXACTLY (warp-per-row, 8 ch/lane
// via float4, all constants hoisted to registers, grid 1184) + __stcs
// (evict-first) output stores: the R6->R7 A/B showed evict-first stores are
// ~5us faster (output is never re-read; normal stores thrash input lines
// out of L2).

#define C_DIM  256
#define LN_EPS 1e-5f
#define FULL   0xFFFFFFFFu

__global__ __launch_bounds__(256)
void dydwconv_ln_kernel(const float* __restrict__ q,
                        const float* __restrict__ v,
                        const float* __restrict__ Ww,     // [3,256]
                        const float* __restrict__ bw,     // [3]
                        const float* __restrict__ gamma,  // [256]
                        const float* __restrict__ beta,   // [256]
                        float* __restrict__ out,
                        int rows, int total_warps)
{
    const int warp_g = (blockIdx.x * blockDim.x + threadIdx.x) >> 5;
    const int lane   = threadIdx.x & 31;
    const int cbase  = lane * 8;               // first channel owned by this lane

    // ---- hoisted constants (registers) ----
    float W0[8], W1[8], W2[8], G[8], Bt[8];
    {
        const float4* p;
        p = (const float4*)(Ww + 0 * C_DIM + cbase);
        float4 a = p[0], b = p[1];
        W0[0]=a.x; W0[1]=a.y; W0[2]=a.z; W0[3]=a.w; W0[4]=b.x; W0[5]=b.y; W0[6]=b.z; W0[7]=b.w;
        p = (const float4*)(Ww + 1 * C_DIM + cbase);
        a = p[0]; b = p[1];
        W1[0]=a.x; W1[1]=a.y; W1[2]=a.z; W1[3]=a.w; W1[4]=b.x; W1[5]=b.y; W1[6]=b.z; W1[7]=b.w;
        p = (const float4*)(Ww + 2 * C_DIM + cbase);
        a = p[0]; b = p[1];
        W2[0]=a.x; W2[1]=a.y; W2[2]=a.z; W2[3]=a.w; W2[4]=b.x; W2[5]=b.y; W2[6]=b.z; W2[7]=b.w;
        p = (const float4*)(gamma + cbase);
        a = p[0]; b = p[1];
        G[0]=a.x; G[1]=a.y; G[2]=a.z; G[3]=a.w; G[4]=b.x; G[5]=b.y; G[6]=b.z; G[7]=b.w;
        p = (const float4*)(beta + cbase);
        a = p[0]; b = p[1];
        Bt[0]=a.x; Bt[1]=a.y; Bt[2]=a.z; Bt[3]=a.w; Bt[4]=b.x; Bt[5]=b.y; Bt[6]=b.z; Bt[7]=b.w;
    }
    const float bw0 = bw[0], bw1 = bw[1], bw2 = bw[2];

    for (int row = warp_g; row < rows; row += total_warps) {
        const size_t base = (size_t)row * C_DIM + cbase;

        float Q[8], V[8];
        {
            const float4* qp = (const float4*)(q + base);
            float4 a = qp[0], b = qp[1];
            Q[0]=a.x; Q[1]=a.y; Q[2]=a.z; Q[3]=a.w; Q[4]=b.x; Q[5]=b.y; Q[6]=b.z; Q[7]=b.w;
            const float4* vp = (const float4*)(v + base);
            a = vp[0]; b = vp[1];
            V[0]=a.x; V[1]=a.y; V[2]=a.z; V[3]=a.w; V[4]=b.x; V[5]=b.y; V[6]=b.z; V[7]=b.w;
        }

        // ---- dynamic kernel weights: w_k = bw[k] + sum_c q[c]*Ww[k][c] ----
        float p0 = 0.f, p1 = 0.f, p2 = 0.f;
        #pragma unroll
        for (int i = 0; i < 8; i++) {
            p0 = fmaf(Q[i], W0[i], p0);
            p1 = fmaf(Q[i], W1[i], p1);
            p2 = fmaf(Q[i], W2[i], p2);
        }
        #pragma unroll
        for (int off = 16; off > 0; off >>= 1) {
            p0 += __shfl_xor_sync(FULL, p0, off);
            p1 += __shfl_xor_sync(FULL, p1, off);
            p2 += __shfl_xor_sync(FULL, p2, off);
        }
        const float w0 = bw0 + p0;
        const float w1 = bw1 + p1;
        const float w2 = bw2 + p2;

        // ---- halo exchange for 3-tap conv (zero padded) ----
        float vl = __shfl_up_sync(FULL, V[7], 1);    // channel cbase-1
        float vr = __shfl_down_sync(FULL, V[0], 1);  // channel cbase+8
        if (lane == 0)  vl = 0.f;
        if (lane == 31) vr = 0.f;

        float O[8];
        O[0] = vl * w0 + V[0] * w1 + V[1] * w2;
        #pragma unroll
        for (int i = 1; i < 7; i++)
            O[i] = V[i - 1] * w0 + V[i] * w1 + V[i + 1] * w2;
        O[7] = V[6] * w0 + V[7] * w1 + vr * w2;

        // ---- LayerNorm over 256 channels ----
        float s = 0.f, ss = 0.f;
        #pragma unroll
        for (int i = 0; i < 8; i++) {
            s += O[i];
            ss = fmaf(O[i], O[i], ss);
        }
        #pragma unroll
        for (int off = 16; off > 0; off >>= 1) {
            s  += __shfl_xor_sync(FULL, s,  off);
            ss += __shfl_xor_sync(FULL, ss, off);
        }
        const float mean = s  * (1.0f / C_DIM);
        const float var  = ss * (1.0f / C_DIM) - mean * mean;
        const float inv  = rsqrtf(var + LN_EPS);

        float4 o0, o1;
        o0.x = (O[0] - mean) * inv * G[0] + Bt[0];
        o0.y = (O[1] - mean) * inv * G[1] + Bt[1];
        o0.z = (O[2] - mean) * inv * G[2] + Bt[2];
        o0.w = (O[3] - mean) * inv * G[3] + Bt[3];
        o1.x = (O[4] - mean) * inv * G[4] + Bt[4];
        o1.y = (O[5] - mean) * inv * G[5] + Bt[5];
        o1.z = (O[6] - mean) * inv * G[6] + Bt[6];
        o1.w = (O[7] - mean) * inv * G[7] + Bt[7];
        __stcs((float4*)(out + base),     o0);   // evict-first: never re-read
        __stcs((float4*)(out + base) + 1, o1);
    }
}

extern "C" void kernel_launch(void* const* d_in, const int* in_sizes, int n_in,
                              void* d_out, int out_size)
{
    const float* q     = (const float*)d_in[0];
    const float* v     = (const float*)d_in[1];
    const float* Ww    = (const float*)d_in[2];
    const float* bw    = (const float*)d_in[3];
    const float* gamma = (const float*)d_in[4];
    const float* beta  = (const float*)d_in[5];
    float* out = (float*)d_out;

    const int rows = in_sizes[0] / C_DIM;        // 102400
    const int grid = 1184;                       // 148 SMs * 8 CTAs
    const int total_warps = grid * (256 / 32);   // 9472 -> ~10.8 rows/warp
    dydwconv_ln_kernel<<<grid, 256>>>(q, v, Ww, bw, gamma, beta, out,
                                      rows, total_warps);
}